// round 2
// baseline (speedup 1.0000x reference)
#include <cuda_runtime.h>

// Problem constants
#define TLEN 2048
#define BSZ  2
#define EMB  1024
#define NH   16
#define HD   64
#define BH   (BSZ*NH)     // 32
#define MROWS (TLEN*BSZ)  // 4096
#define THREE_E (3*EMB)   // 3072
#define SCALING 0.125f    // 64^-0.5

// Scratch (allocations are forbidden; use device globals). 4 x 16 MB.
__device__ float g_q[BH*TLEN*HD];
__device__ float g_k[BH*TLEN*HD];
__device__ float g_v[BH*TLEN*HD];
__device__ float g_attn[BH*TLEN*HD];

// ---------------------------------------------------------------------------
// Kernel 1: QKV projection.  C[m,f] = sum_e X[m,e]*W[f,e] + bias[f]
// X: [4096,1024] row-major (m = t*B + b), W: [3072,1024] row-major.
// Epilogue scatters into g_q/g_k/g_v laid out [BH][T][D]; q scaled by 0.125.
// ---------------------------------------------------------------------------
__global__ __launch_bounds__(256) void qkv_kernel(const float* __restrict__ X,
                                                  const float* __restrict__ W,
                                                  const float* __restrict__ bias) {
    __shared__ float As[8][128];
    __shared__ float Bs[8][128];
    const int tid = threadIdx.x;
    const int tx = tid & 15, ty = tid >> 4;
    const int lr = tid >> 1;
    const int lc = (tid & 1) * 4;
    const float* Ap = X + (blockIdx.y * 128 + lr) * EMB + lc;
    const float* Bp = W + (blockIdx.x * 128 + lr) * EMB + lc;

    float acc[8][8];
    #pragma unroll
    for (int i = 0; i < 8; i++)
        #pragma unroll
        for (int j = 0; j < 8; j++) acc[i][j] = 0.0f;

    for (int k0 = 0; k0 < EMB; k0 += 8) {
        float4 a4 = *(const float4*)(Ap + k0);
        float4 b4 = *(const float4*)(Bp + k0);
        As[lc+0][lr] = a4.x; As[lc+1][lr] = a4.y; As[lc+2][lr] = a4.z; As[lc+3][lr] = a4.w;
        Bs[lc+0][lr] = b4.x; Bs[lc+1][lr] = b4.y; Bs[lc+2][lr] = b4.z; Bs[lc+3][lr] = b4.w;
        __syncthreads();
        #pragma unroll
        for (int k = 0; k < 8; k++) {
            float a[8], b[8];
            *(float4*)(a)     = *(const float4*)&As[k][ty*8];
            *(float4*)(a + 4) = *(const float4*)&As[k][ty*8 + 4];
            *(float4*)(b)     = *(const float4*)&Bs[k][tx*8];
            *(float4*)(b + 4) = *(const float4*)&Bs[k][tx*8 + 4];
            #pragma unroll
            for (int i = 0; i < 8; i++)
                #pragma unroll
                for (int j = 0; j < 8; j++)
                    acc[i][j] = fmaf(a[i], b[j], acc[i][j]);
        }
        __syncthreads();
    }

    // Epilogue: 8 consecutive f per thread stay within one (section, head).
    const int f0  = blockIdx.x * 128 + tx * 8;
    const int sec = f0 >> 10;           // 0=q,1=k,2=v
    const int e2  = f0 & 1023;
    const int h   = e2 >> 6, d0 = e2 & 63;
    const float scale = (sec == 0) ? SCALING : 1.0f;
    float* dstb = (sec == 0) ? g_q : (sec == 1) ? g_k : g_v;
    float bv[8];
    #pragma unroll
    for (int j = 0; j < 8; j++) bv[j] = bias[f0 + j];

    #pragma unroll
    for (int i = 0; i < 8; i++) {
        const int m = blockIdx.y * 128 + ty * 8 + i;
        const int t = m >> 1, b = m & 1;
        float* dst = dstb + ((((b << 4) + h) * TLEN + t) * HD + d0);
        float4 o;
        o.x = (acc[i][0] + bv[0]) * scale;
        o.y = (acc[i][1] + bv[1]) * scale;
        o.z = (acc[i][2] + bv[2]) * scale;
        o.w = (acc[i][3] + bv[3]) * scale;
        *(float4*)dst = o;
        o.x = (acc[i][4] + bv[4]) * scale;
        o.y = (acc[i][5] + bv[5]) * scale;
        o.z = (acc[i][6] + bv[6]) * scale;
        o.w = (acc[i][7] + bv[7]) * scale;
        *(float4*)(dst + 4) = o;
    }
}

// ---------------------------------------------------------------------------
// Kernel 2: flash-style attention, one block per (head, 128-query tile).
// ---------------------------------------------------------------------------
struct __align__(16) AttnSmem {
    float Qs[64][128];    // [d][row]
    float Ks[64][128];    // [d][key]
    float Vs[128][68];    // [key][d] (padded)
    float Ps[128][132];   // [row][key] (padded)
    float red[128][17];   // row-reduction workspace (padded: conflict-free)
    float mbuf[128];
    float abuf[128];
    float lbuf[128];
};

__global__ __launch_bounds__(256, 1) void attn_kernel() {
    extern __shared__ char smraw[];
    AttnSmem& sm = *reinterpret_cast<AttnSmem*>(smraw);
    const int tid = threadIdx.x;
    const int tx = tid & 15, ty = tid >> 4;          // S-gemm layout (8x8 frag)
    const int lane = tid & 31, w = tid >> 5;         // PV layout
    const int rr = lane >> 4, dd = lane & 15;
    const int pr0 = w * 16 + rr * 8;                 // 8 rows per thread
    const int pd0 = dd * 4;                          // 4 cols per thread
    const int head = blockIdx.y;
    const int qbase = blockIdx.x * 128;

    const float* Qg = g_q + (head * TLEN + qbase) * HD;
    const float* Kg = g_k + head * TLEN * HD;
    const float* Vg = g_v + head * TLEN * HD;

    // Load Q tile (transposed into [d][row])
    #pragma unroll
    for (int i = 0; i < 8; i++) {
        int idx = tid + i * 256;
        int r = idx >> 4;
        int d4 = (idx & 15) << 2;
        float4 v = *(const float4*)(Qg + r * HD + d4);
        sm.Qs[d4+0][r] = v.x; sm.Qs[d4+1][r] = v.y;
        sm.Qs[d4+2][r] = v.z; sm.Qs[d4+3][r] = v.w;
    }
    if (tid < 128) { sm.mbuf[tid] = -3.0e38f; sm.lbuf[tid] = 0.0f; }
    float O[8][4] = {};
    __syncthreads();

    for (int kt = 0; kt < TLEN / 128; kt++) {
        const float* Kt = Kg + kt * 128 * HD;
        const float* Vt = Vg + kt * 128 * HD;
        #pragma unroll
        for (int i = 0; i < 8; i++) {
            int idx = tid + i * 256;
            int r = idx >> 4;
            int d4 = (idx & 15) << 2;
            float4 kv = *(const float4*)(Kt + r * HD + d4);
            sm.Ks[d4+0][r] = kv.x; sm.Ks[d4+1][r] = kv.y;
            sm.Ks[d4+2][r] = kv.z; sm.Ks[d4+3][r] = kv.w;
            float4 vv = *(const float4*)(Vt + r * HD + d4);
            *(float4*)&sm.Vs[r][d4] = vv;
        }
        __syncthreads();

        // S = Q K^T  (q already scaled)
        float sf[8][8];
        #pragma unroll
        for (int i = 0; i < 8; i++)
            #pragma unroll
            for (int j = 0; j < 8; j++) sf[i][j] = 0.0f;
        const int r0 = ty * 8, c0 = tx * 8;
        #pragma unroll 8
        for (int kk = 0; kk < 64; kk++) {
            float a[8], b[8];
            *(float4*)(a)     = *(const float4*)&sm.Qs[kk][r0];
            *(float4*)(a + 4) = *(const float4*)&sm.Qs[kk][r0 + 4];
            *(float4*)(b)     = *(const float4*)&sm.Ks[kk][c0];
            *(float4*)(b + 4) = *(const float4*)&sm.Ks[kk][c0 + 4];
            #pragma unroll
            for (int i = 0; i < 8; i++)
                #pragma unroll
                for (int j = 0; j < 8; j++)
                    sf[i][j] = fmaf(a[i], b[j], sf[i][j]);
        }

        // Partial row-max
        #pragma unroll
        for (int i = 0; i < 8; i++) {
            float mx = sf[i][0];
            #pragma unroll
            for (int j = 1; j < 8; j++) mx = fmaxf(mx, sf[i][j]);
            sm.red[r0 + i][tx] = mx;
        }
        __syncthreads();
        if (tid < 128) {
            float mx = sm.red[tid][0];
            #pragma unroll
            for (int k = 1; k < 16; k++) mx = fmaxf(mx, sm.red[tid][k]);
            float mo = sm.mbuf[tid];
            float mn = fmaxf(mo, mx);
            sm.mbuf[tid] = mn;
            sm.abuf[tid] = __expf(mo - mn);
        }
        __syncthreads();

        // P = exp(S - m), write Ps, partial row-sums
        #pragma unroll
        for (int i = 0; i < 8; i++) {
            float mn = sm.mbuf[r0 + i];
            float p[8], psum = 0.0f;
            #pragma unroll
            for (int j = 0; j < 8; j++) { p[j] = __expf(sf[i][j] - mn); psum += p[j]; }
            *(float4*)&sm.Ps[r0 + i][c0]     = make_float4(p[0], p[1], p[2], p[3]);
            *(float4*)&sm.Ps[r0 + i][c0 + 4] = make_float4(p[4], p[5], p[6], p[7]);
            sm.red[r0 + i][tx] = psum;
        }
        __syncthreads();
        if (tid < 128) {
            float sum = 0.0f;
            #pragma unroll
            for (int k = 0; k < 16; k++) sum += sm.red[tid][k];
            sm.lbuf[tid] = sm.lbuf[tid] * sm.abuf[tid] + sum;
        }

        // O = O*alpha + P @ V
        float al[8];
        #pragma unroll
        for (int i = 0; i < 8; i++) al[i] = sm.abuf[pr0 + i];
        #pragma unroll
        for (int i = 0; i < 8; i++)
            #pragma unroll
            for (int j = 0; j < 4; j++) O[i][j] *= al[i];
        #pragma unroll 8
        for (int j = 0; j < 128; j++) {
            float pa[8];
            #pragma unroll
            for (int i = 0; i < 8; i++) pa[i] = sm.Ps[pr0 + i][j];
            float4 vb = *(const float4*)&sm.Vs[j][pd0];
            #pragma unroll
            for (int i = 0; i < 8; i++) {
                O[i][0] = fmaf(pa[i], vb.x, O[i][0]);
                O[i][1] = fmaf(pa[i], vb.y, O[i][1]);
                O[i][2] = fmaf(pa[i], vb.z, O[i][2]);
                O[i][3] = fmaf(pa[i], vb.w, O[i][3]);
            }
        }
        __syncthreads();
    }

    float* Og = g_attn + (head * TLEN + qbase) * HD;
    #pragma unroll
    for (int i = 0; i < 8; i++) {
        float inv = 1.0f / sm.lbuf[pr0 + i];
        float4 o = make_float4(O[i][0] * inv, O[i][1] * inv,
                               O[i][2] * inv, O[i][3] * inv);
        *(float4*)(Og + (pr0 + i) * HD + pd0) = o;
    }
}

// ---------------------------------------------------------------------------
// Kernel 3: output projection. out[m,f] = sum_e attn[m,e]*Wout[f,e] + bias[f]
// attn gathered from g_attn [BH][T][D] (e = h*64 + d, m = t*2 + b).
// ---------------------------------------------------------------------------
__global__ __launch_bounds__(256) void outproj_kernel(const float* __restrict__ W,
                                                      const float* __restrict__ bias,
                                                      float* __restrict__ out) {
    __shared__ float As[8][128];
    __shared__ float Bs[8][128];
    const int tid = threadIdx.x;
    const int tx = tid & 15, ty = tid >> 4;
    const int lr = tid >> 1;
    const int lc = (tid & 1) * 4;
    const int mA = blockIdx.y * 128 + lr;
    const int tA = mA >> 1, bA = mA & 1;
    const float* Bp = W + (blockIdx.x * 128 + lr) * EMB + lc;

    float acc[8][8];
    #pragma unroll
    for (int i = 0; i < 8; i++)
        #pragma unroll
        for (int j = 0; j < 8; j++) acc[i][j] = 0.0f;

    for (int k0 = 0; k0 < EMB; k0 += 8) {
        const int e = k0 + lc;
        const float* Ap = g_attn + ((((bA << 4) + (e >> 6)) * TLEN + tA) * HD + (e & 63));
        float4 a4 = *(const float4*)Ap;
        float4 b4 = *(const float4*)(Bp + k0);
        As[lc+0][lr] = a4.x; As[lc+1][lr] = a4.y; As[lc+2][lr] = a4.z; As[lc+3][lr] = a4.w;
        Bs[lc+0][lr] = b4.x; Bs[lc+1][lr] = b4.y; Bs[lc+2][lr] = b4.z; Bs[lc+3][lr] = b4.w;
        __syncthreads();
        #pragma unroll
        for (int k = 0; k < 8; k++) {
            float a[8], b[8];
            *(float4*)(a)     = *(const float4*)&As[k][ty*8];
            *(float4*)(a + 4) = *(const float4*)&As[k][ty*8 + 4];
            *(float4*)(b)     = *(const float4*)&Bs[k][tx*8];
            *(float4*)(b + 4) = *(const float4*)&Bs[k][tx*8 + 4];
            #pragma unroll
            for (int i = 0; i < 8; i++)
                #pragma unroll
                for (int j = 0; j < 8; j++)
                    acc[i][j] = fmaf(a[i], b[j], acc[i][j]);
        }
        __syncthreads();
    }

    const int f0 = blockIdx.x * 128 + tx * 8;
    float bv[8];
    #pragma unroll
    for (int j = 0; j < 8; j++) bv[j] = bias[f0 + j];
    #pragma unroll
    for (int i = 0; i < 8; i++) {
        const int m = blockIdx.y * 128 + ty * 8 + i;
        float* dst = out + m * EMB + f0;
        float4 o;
        o.x = acc[i][0] + bv[0]; o.y = acc[i][1] + bv[1];
        o.z = acc[i][2] + bv[2]; o.w = acc[i][3] + bv[3];
        *(float4*)dst = o;
        o.x = acc[i][4] + bv[4]; o.y = acc[i][5] + bv[5];
        o.z = acc[i][6] + bv[6]; o.w = acc[i][7] + bv[7];
        *(float4*)(dst + 4) = o;
    }
}

// ---------------------------------------------------------------------------
extern "C" void kernel_launch(void* const* d_in, const int* in_sizes, int n_in,
                              void* d_out, int out_size) {
    (void)in_sizes; (void)n_in; (void)out_size;
    const float* x     = (const float*)d_in[0];
    const float* w_in  = (const float*)d_in[1];
    const float* b_in  = (const float*)d_in[2];
    const float* w_out = (const float*)d_in[3];
    const float* b_out = (const float*)d_in[4];
    float* out = (float*)d_out;

    cudaFuncSetAttribute(attn_kernel, cudaFuncAttributeMaxDynamicSharedMemorySize,
                         (int)sizeof(AttnSmem));

    qkv_kernel<<<dim3(THREE_E / 128, MROWS / 128), 256, 0, 0>>>(x, w_in, b_in);
    attn_kernel<<<dim3(TLEN / 128, BH), 256, sizeof(AttnSmem), 0>>>();
    outproj_kernel<<<dim3(EMB / 128, MROWS / 128), 256, 0, 0>>>(w_out, b_out, out);
}

// round 4
// speedup vs baseline: 1.2829x; 1.2829x over previous
#include <cuda_runtime.h>
#include <cuda_bf16.h>
#include <cstdint>

// Problem constants
#define TLEN 2048
#define BSZ  2
#define EMB  1024
#define NH   16
#define HD   64
#define BH   (BSZ*NH)     // 32
#define MROWS (TLEN*BSZ)  // 4096
#define THREE_E (3*EMB)   // 3072
#define KEFF  (3*EMB)     // tripled K for bf16x3 emulation (=3072)
#define KROWB (KEFF*2)    // bytes per row of converted operands (6144)
#define SCALING 0.125f

// ---------------------------------------------------------------------------
// Device-global scratch (allocations forbidden)
// ---------------------------------------------------------------------------
__device__ float g_q[BH*TLEN*HD];
__device__ float g_k[BH*TLEN*HD];
__device__ float g_v[BH*TLEN*HD];
__device__ float g_attn[MROWS*EMB];                 // row-major [m][e]
__device__ __nv_bfloat16 g_xa   [MROWS  * KEFF];    // X,    A-pattern (hi,hi,lo)
__device__ __nv_bfloat16 g_win  [THREE_E* KEFF];    // Win,  B-pattern (hi,lo,hi)
__device__ __nv_bfloat16 g_wout [EMB    * KEFF];    // Wout, B-pattern
__device__ __nv_bfloat16 g_attna[MROWS  * KEFF];    // attn, A-pattern

// ---------------------------------------------------------------------------
// PTX helpers — sm_100 base-target only (no tcgen05 anywhere)
// ---------------------------------------------------------------------------
__device__ __forceinline__ uint32_t smem_u32(const void* p) {
    uint32_t a;
    asm("{ .reg .u64 t; cvta.to.shared.u64 t, %1; cvt.u32.u64 %0, t; }" : "=r"(a) : "l"(p));
    return a;
}
#define CP_ASYNC16(dst, src) \
    asm volatile("cp.async.cg.shared.global [%0], [%1], 16;" :: "r"(dst), "l"(src))
#define CP_COMMIT() asm volatile("cp.async.commit_group;" ::: "memory")
#define CP_WAIT0()  asm volatile("cp.async.wait_group 0;" ::: "memory")
#define CP_WAIT1()  asm volatile("cp.async.wait_group 1;" ::: "memory")

#define LDSM_X4(r0, r1, r2, r3, addr) \
    asm volatile("ldmatrix.sync.aligned.m8n8.x4.shared.b16 {%0,%1,%2,%3}, [%4];" \
        : "=r"(r0), "=r"(r1), "=r"(r2), "=r"(r3) : "r"(addr))

#define MMA16816(d, a, b) \
    asm volatile("mma.sync.aligned.m16n8k16.row.col.f32.bf16.bf16.f32 " \
        "{%0,%1,%2,%3}, {%4,%5,%6,%7}, {%8,%9}, {%0,%1,%2,%3};" \
        : "+f"((d)[0]), "+f"((d)[1]), "+f"((d)[2]), "+f"((d)[3]) \
        : "r"((a)[0]), "r"((a)[1]), "r"((a)[2]), "r"((a)[3]), \
          "r"((b)[0]), "r"((b)[1]))

// ---------------------------------------------------------------------------
// Conversion: fp32 [rows x 1024] -> bf16x3 [rows x 3072].
// patB=0 (A-pattern): segs hi,hi,lo.  patB=1 (B-pattern): segs hi,lo,hi.
// ---------------------------------------------------------------------------
__global__ __launch_bounds__(256) void cvt_kernel(const float* __restrict__ src,
                                                  __nv_bfloat16* __restrict__ dst,
                                                  int patB) {
    const int row = blockIdx.x;
    const int kc = threadIdx.x * 4;
    float4 v = *(const float4*)(src + row * EMB + kc);
    __nv_bfloat16 h[4], l[4];
    float f[4] = {v.x, v.y, v.z, v.w};
    #pragma unroll
    for (int j = 0; j < 4; j++) {
        h[j] = __float2bfloat16(f[j]);
        l[j] = __float2bfloat16(f[j] - __bfloat162float(h[j]));
    }
    uint32_t hp0, hp1, lp0, lp1;
    asm("mov.b32 %0, {%1, %2};" : "=r"(hp0) : "h"(*(unsigned short*)&h[0]), "h"(*(unsigned short*)&h[1]));
    asm("mov.b32 %0, {%1, %2};" : "=r"(hp1) : "h"(*(unsigned short*)&h[2]), "h"(*(unsigned short*)&h[3]));
    asm("mov.b32 %0, {%1, %2};" : "=r"(lp0) : "h"(*(unsigned short*)&l[0]), "h"(*(unsigned short*)&l[1]));
    asm("mov.b32 %0, {%1, %2};" : "=r"(lp1) : "h"(*(unsigned short*)&l[2]), "h"(*(unsigned short*)&l[3]));
    uint2 hv = make_uint2(hp0, hp1);
    uint2 lv = make_uint2(lp0, lp1);
    __nv_bfloat16* base = dst + row * KEFF + kc;
    *(uint2*)(base)            = hv;                    // seg0: hi
    *(uint2*)(base + EMB)      = patB ? lv : hv;        // seg1
    *(uint2*)(base + 2 * EMB)  = patB ? hv : lv;        // seg2
}

// ---------------------------------------------------------------------------
// mma.sync bf16 GEMM:  C[m][n] = sum_k A[m][k]*B[n][k], K=3072.
// Block tile 128x128, 8 warps (2x4), warp tile 64x32, K-chunk 32, 2-stage.
// MODE 0: qkv epilogue (scatter g_q/g_k/g_v, q scaled). MODE 1: plain + bias.
// ---------------------------------------------------------------------------
#define TILE_M 128
#define TILE_N 128
#define KCH 32
#define NCHUNK (KEFF / KCH)   // 96
#define ASTRIDE 40            // bf16 elems per smem row (80 B: conflict-free ldmatrix)

template <int MODE>
__global__ __launch_bounds__(256, 1) void gemm_kernel(const __nv_bfloat16* __restrict__ A,
                                                      const __nv_bfloat16* __restrict__ B,
                                                      const float* __restrict__ bias,
                                                      float* __restrict__ out) {
    __shared__ __align__(16) __nv_bfloat16 sA[2][TILE_M * ASTRIDE];
    __shared__ __align__(16) __nv_bfloat16 sB[2][TILE_N * ASTRIDE];

    const int tid = threadIdx.x;
    const int wid = tid >> 5, lane = tid & 31;
    const int m0 = blockIdx.y * TILE_M;
    const int n0 = blockIdx.x * TILE_N;
    const int warp_m = (wid >> 2) * 64;
    const int warp_n = (wid & 3) * 32;

    const char* Ab = (const char*)A + (size_t)m0 * KROWB;
    const char* Bb = (const char*)B + (size_t)n0 * KROWB;
    const uint32_t sbA = smem_u32(sA);
    const uint32_t sbB = smem_u32(sB);

    // per-lane ldmatrix address components
    const int a_row = lane & 15;
    const int a_kof = (lane >> 4) << 3;
    const int b_row = (lane & 7) + ((lane & 16) >> 1);   // +8 for lanes 16-31
    const int b_kof = ((lane >> 3) & 1) << 3;

    float acc[4][4][4];
    #pragma unroll
    for (int i = 0; i < 4; i++)
        #pragma unroll
        for (int j = 0; j < 4; j++)
            #pragma unroll
            for (int r = 0; r < 4; r++) acc[i][j][r] = 0.0f;

    auto load_chunk = [&](int c, int s) {
        const uint32_t da = sbA + s * (TILE_M * ASTRIDE * 2);
        const uint32_t db = sbB + s * (TILE_N * ASTRIDE * 2);
        const size_t ko = (size_t)c * (KCH * 2);
        #pragma unroll
        for (int i = 0; i < 2; i++) {                 // A: 128 rows x 4 x 16B
            int u = tid + i * 256;
            int r = u >> 2, seg = (u & 3) * 16;
            CP_ASYNC16(da + r * (ASTRIDE * 2) + seg, Ab + (size_t)r * KROWB + ko + seg);
        }
        #pragma unroll
        for (int i = 0; i < 2; i++) {                 // B: 128 rows x 4 x 16B
            int u = tid + i * 256;
            int r = u >> 2, seg = (u & 3) * 16;
            CP_ASYNC16(db + r * (ASTRIDE * 2) + seg, Bb + (size_t)r * KROWB + ko + seg);
        }
        CP_COMMIT();
    };

    load_chunk(0, 0);
    int s = 0;
    for (int c = 0; c < NCHUNK; c++) {
        if (c + 1 < NCHUNK) { load_chunk(c + 1, s ^ 1); CP_WAIT1(); }
        else CP_WAIT0();
        __syncthreads();

        const uint32_t da = sbA + s * (TILE_M * ASTRIDE * 2);
        const uint32_t db = sbB + s * (TILE_N * ASTRIDE * 2);
        #pragma unroll
        for (int k0 = 0; k0 < KCH; k0 += 16) {
            uint32_t af[4][4], bf[4][2];
            #pragma unroll
            for (int i = 0; i < 4; i++) {
                uint32_t addr = da + (warp_m + i * 16 + a_row) * (ASTRIDE * 2)
                              + (k0 + a_kof) * 2;
                LDSM_X4(af[i][0], af[i][1], af[i][2], af[i][3], addr);
            }
            #pragma unroll
            for (int j2 = 0; j2 < 2; j2++) {
                uint32_t addr = db + (warp_n + j2 * 16 + b_row) * (ASTRIDE * 2)
                              + (k0 + b_kof) * 2;
                LDSM_X4(bf[j2*2][0], bf[j2*2][1], bf[j2*2+1][0], bf[j2*2+1][1], addr);
            }
            #pragma unroll
            for (int i = 0; i < 4; i++)
                #pragma unroll
                for (int j = 0; j < 4; j++)
                    MMA16816(acc[i][j], af[i], bf[j]);
        }
        __syncthreads();
        s ^= 1;
    }

    // Epilogue
    const int sec = n0 >> 10;
    const float sc = (MODE == 0 && sec == 0) ? SCALING : 1.0f;
    float* secp = (sec == 0) ? g_q : (sec == 1) ? g_k : g_v;

    #pragma unroll
    for (int i = 0; i < 4; i++) {
        #pragma unroll
        for (int j = 0; j < 4; j++) {
            const int f = n0 + warp_n + j * 8 + (lane & 3) * 2;
            const float b0 = bias[f], b1 = bias[f + 1];
            #pragma unroll
            for (int half = 0; half < 2; half++) {
                const int m = m0 + warp_m + i * 16 + (lane >> 2) + half * 8;
                float2 o;
                o.x = (acc[i][j][half * 2 + 0] + b0) * sc;
                o.y = (acc[i][j][half * 2 + 1] + b1) * sc;
                if (MODE == 0) {
                    const int t = m >> 1, bq = m & 1;
                    const int rel = f & 1023, h = rel >> 6, d = rel & 63;
                    *(float2*)(secp + ((((bq << 4) + h) * TLEN + t) * HD + d)) = o;
                } else {
                    *(float2*)(out + (size_t)m * EMB + f) = o;
                }
            }
        }
    }
}

// ---------------------------------------------------------------------------
// Flash attention (fp32 SIMT; output row-major g_attn[m][e])
// ---------------------------------------------------------------------------
struct __align__(16) AttnSmem {
    float Qs[64][128];
    float Ks[64][128];
    float Vs[128][68];
    float Ps[128][132];
    float red[128][17];
    float mbuf[128];
    float abuf[128];
    float lbuf[128];
};

__global__ __launch_bounds__(256, 1) void attn_kernel() {
    extern __shared__ char smraw[];
    AttnSmem& sm = *reinterpret_cast<AttnSmem*>(smraw);
    const int tid = threadIdx.x;
    const int tx = tid & 15, ty = tid >> 4;
    const int lane = tid & 31, w = tid >> 5;
    const int rr = lane >> 4, dd = lane & 15;
    const int pr0 = w * 16 + rr * 8;
    const int pd0 = dd * 4;
    const int head = blockIdx.y;
    const int qbase = blockIdx.x * 128;

    const float* Qg = g_q + (head * TLEN + qbase) * HD;
    const float* Kg = g_k + head * TLEN * HD;
    const float* Vg = g_v + head * TLEN * HD;

    #pragma unroll
    for (int i = 0; i < 8; i++) {
        int idx = tid + i * 256;
        int r = idx >> 4;
        int d4 = (idx & 15) << 2;
        float4 v = *(const float4*)(Qg + r * HD + d4);
        sm.Qs[d4+0][r] = v.x; sm.Qs[d4+1][r] = v.y;
        sm.Qs[d4+2][r] = v.z; sm.Qs[d4+3][r] = v.w;
    }
    if (tid < 128) { sm.mbuf[tid] = -3.0e38f; sm.lbuf[tid] = 0.0f; }
    float O[8][4] = {};
    __syncthreads();

    for (int kt = 0; kt < TLEN / 128; kt++) {
        const float* Kt = Kg + kt * 128 * HD;
        const float* Vt = Vg + kt * 128 * HD;
        #pragma unroll
        for (int i = 0; i < 8; i++) {
            int idx = tid + i * 256;
            int r = idx >> 4;
            int d4 = (idx & 15) << 2;
            float4 kv = *(const float4*)(Kt + r * HD + d4);
            sm.Ks[d4+0][r] = kv.x; sm.Ks[d4+1][r] = kv.y;
            sm.Ks[d4+2][r] = kv.z; sm.Ks[d4+3][r] = kv.w;
            float4 vv = *(const float4*)(Vt + r * HD + d4);
            *(float4*)&sm.Vs[r][d4] = vv;
        }
        __syncthreads();

        float sf[8][8];
        #pragma unroll
        for (int i = 0; i < 8; i++)
            #pragma unroll
            for (int j = 0; j < 8; j++) sf[i][j] = 0.0f;
        const int r0 = ty * 8, c0 = tx * 8;
        #pragma unroll 8
        for (int kk = 0; kk < 64; kk++) {
            float a[8], b[8];
            *(float4*)(a)     = *(const float4*)&sm.Qs[kk][r0];
            *(float4*)(a + 4) = *(const float4*)&sm.Qs[kk][r0 + 4];
            *(float4*)(b)     = *(const float4*)&sm.Ks[kk][c0];
            *(float4*)(b + 4) = *(const float4*)&sm.Ks[kk][c0 + 4];
            #pragma unroll
            for (int i = 0; i < 8; i++)
                #pragma unroll
                for (int j = 0; j < 8; j++)
                    sf[i][j] = fmaf(a[i], b[j], sf[i][j]);
        }

        #pragma unroll
        for (int i = 0; i < 8; i++) {
            float mx = sf[i][0];
            #pragma unroll
            for (int j = 1; j < 8; j++) mx = fmaxf(mx, sf[i][j]);
            sm.red[r0 + i][tx] = mx;
        }
        __syncthreads();
        if (tid < 128) {
            float mx = sm.red[tid][0];
            #pragma unroll
            for (int k = 1; k < 16; k++) mx = fmaxf(mx, sm.red[tid][k]);
            float mo = sm.mbuf[tid];
            float mn = fmaxf(mo, mx);
            sm.mbuf[tid] = mn;
            sm.abuf[tid] = __expf(mo - mn);
        }
        __syncthreads();

        #pragma unroll
        for (int i = 0; i < 8; i++) {
            float mn = sm.mbuf[r0 + i];
            float p[8], psum = 0.0f;
            #pragma unroll
            for (int j = 0; j < 8; j++) { p[j] = __expf(sf[i][j] - mn); psum += p[j]; }
            *(float4*)&sm.Ps[r0 + i][c0]     = make_float4(p[0], p[1], p[2], p[3]);
            *(float4*)&sm.Ps[r0 + i][c0 + 4] = make_float4(p[4], p[5], p[6], p[7]);
            sm.red[r0 + i][tx] = psum;
        }
        __syncthreads();
        if (tid < 128) {
            float sum = 0.0f;
            #pragma unroll
            for (int k = 0; k < 16; k++) sum += sm.red[tid][k];
            sm.lbuf[tid] = sm.lbuf[tid] * sm.abuf[tid] + sum;
        }

        float al[8];
        #pragma unroll
        for (int i = 0; i < 8; i++) al[i] = sm.abuf[pr0 + i];
        #pragma unroll
        for (int i = 0; i < 8; i++)
            #pragma unroll
            for (int j = 0; j < 4; j++) O[i][j] *= al[i];
        #pragma unroll 8
        for (int j = 0; j < 128; j++) {
            float pa[8];
            #pragma unroll
            for (int i = 0; i < 8; i++) pa[i] = sm.Ps[pr0 + i][j];
            float4 vb = *(const float4*)&sm.Vs[j][pd0];
            #pragma unroll
            for (int i = 0; i < 8; i++) {
                O[i][0] = fmaf(pa[i], vb.x, O[i][0]);
                O[i][1] = fmaf(pa[i], vb.y, O[i][1]);
                O[i][2] = fmaf(pa[i], vb.z, O[i][2]);
                O[i][3] = fmaf(pa[i], vb.w, O[i][3]);
            }
        }
        __syncthreads();
    }

    const int b = head >> 4, h = head & 15;
    #pragma unroll
    for (int i = 0; i < 8; i++) {
        float inv = 1.0f / sm.lbuf[pr0 + i];
        float4 o = make_float4(O[i][0] * inv, O[i][1] * inv,
                               O[i][2] * inv, O[i][3] * inv);
        const int m = (qbase + pr0 + i) * 2 + b;
        *(float4*)(g_attn + (size_t)m * EMB + h * HD + pd0) = o;
    }
}

// ---------------------------------------------------------------------------
extern "C" void kernel_launch(void* const* d_in, const int* in_sizes, int n_in,
                              void* d_out, int out_size) {
    (void)in_sizes; (void)n_in; (void)out_size;
    const float* x     = (const float*)d_in[0];
    const float* w_in  = (const float*)d_in[1];
    const float* b_in  = (const float*)d_in[2];
    const float* w_out = (const float*)d_in[3];
    const float* b_out = (const float*)d_in[4];
    float* out = (float*)d_out;

    cudaFuncSetAttribute(attn_kernel, cudaFuncAttributeMaxDynamicSharedMemorySize,
                         (int)sizeof(AttnSmem));

    __nv_bfloat16 *gxa, *gwin, *gwout, *gattna;
    float *gattn;
    cudaGetSymbolAddress((void**)&gxa, g_xa);
    cudaGetSymbolAddress((void**)&gwin, g_win);
    cudaGetSymbolAddress((void**)&gwout, g_wout);
    cudaGetSymbolAddress((void**)&gattna, g_attna);
    cudaGetSymbolAddress((void**)&gattn, g_attn);

    // 1) convert operands to bf16x3
    cvt_kernel<<<MROWS, 256>>>(x, gxa, 0);
    cvt_kernel<<<THREE_E, 256>>>(w_in, gwin, 1);
    cvt_kernel<<<EMB, 256>>>(w_out, gwout, 1);
    // 2) QKV projection (mma.sync bf16)
    gemm_kernel<0><<<dim3(THREE_E / TILE_N, MROWS / TILE_M), 256>>>(gxa, gwin, b_in, nullptr);
    // 3) attention (fp32 SIMT)
    attn_kernel<<<dim3(TLEN / 128, BH), 256, sizeof(AttnSmem)>>>();
    // 4) convert attention output, output projection
    cvt_kernel<<<MROWS, 256>>>(gattn, gattna, 0);
    gemm_kernel<1><<<dim3(EMB / TILE_N, MROWS / TILE_M), 256>>>(gattna, gwout, b_out, out);
}

// round 5
// speedup vs baseline: 2.5717x; 2.0046x over previous
#include <cuda_runtime.h>
#include <cuda_bf16.h>
#include <cstdint>

// Problem constants
#define TLEN 2048
#define BSZ  2
#define EMB  1024
#define NH   16
#define HD   64
#define BH   (BSZ*NH)     // 32
#define MROWS (TLEN*BSZ)  // 4096
#define THREE_E (3*EMB)   // 3072
#define KEFF  (3*EMB)     // tripled K for bf16x3 emulation (=3072)
#define KROWB (KEFF*2)    // bytes per row of converted operands (6144)
#define SCALING 0.125f

// ---------------------------------------------------------------------------
// Device-global scratch (allocations forbidden)
// ---------------------------------------------------------------------------
__device__ __nv_bfloat16 g_qh[BH*TLEN*HD];
__device__ __nv_bfloat16 g_ql[BH*TLEN*HD];
__device__ __nv_bfloat16 g_kh[BH*TLEN*HD];
__device__ __nv_bfloat16 g_kl[BH*TLEN*HD];
__device__ __nv_bfloat16 g_vh[BH*TLEN*HD];
__device__ __nv_bfloat16 g_vl[BH*TLEN*HD];
__device__ __nv_bfloat16 g_xa   [MROWS  * KEFF];    // X,    A-pattern (hi,hi,lo)
__device__ __nv_bfloat16 g_win  [THREE_E* KEFF];    // Win,  B-pattern (hi,lo,hi)
__device__ __nv_bfloat16 g_wout [EMB    * KEFF];    // Wout, B-pattern
__device__ __nv_bfloat16 g_attna[MROWS  * KEFF];    // attn, A-pattern

// ---------------------------------------------------------------------------
// PTX helpers — base sm_100 target only
// ---------------------------------------------------------------------------
__device__ __forceinline__ uint32_t smem_u32(const void* p) {
    uint32_t a;
    asm("{ .reg .u64 t; cvta.to.shared.u64 t, %1; cvt.u32.u64 %0, t; }" : "=r"(a) : "l"(p));
    return a;
}
#define CP_ASYNC16(dst, src) \
    asm volatile("cp.async.cg.shared.global [%0], [%1], 16;" :: "r"(dst), "l"(src))
#define CP_COMMIT() asm volatile("cp.async.commit_group;" ::: "memory")
#define CP_WAIT0()  asm volatile("cp.async.wait_group 0;" ::: "memory")
#define CP_WAIT1()  asm volatile("cp.async.wait_group 1;" ::: "memory")

#define LDSM_X4(r0, r1, r2, r3, addr) \
    asm volatile("ldmatrix.sync.aligned.m8n8.x4.shared.b16 {%0,%1,%2,%3}, [%4];" \
        : "=r"(r0), "=r"(r1), "=r"(r2), "=r"(r3) : "r"(addr))
#define LDSM_X4_T(r0, r1, r2, r3, addr) \
    asm volatile("ldmatrix.sync.aligned.m8n8.x4.trans.shared.b16 {%0,%1,%2,%3}, [%4];" \
        : "=r"(r0), "=r"(r1), "=r"(r2), "=r"(r3) : "r"(addr))

#define MMA16816(d, a, b) \
    asm volatile("mma.sync.aligned.m16n8k16.row.col.f32.bf16.bf16.f32 " \
        "{%0,%1,%2,%3}, {%4,%5,%6,%7}, {%8,%9}, {%0,%1,%2,%3};" \
        : "+f"((d)[0]), "+f"((d)[1]), "+f"((d)[2]), "+f"((d)[3]) \
        : "r"((a)[0]), "r"((a)[1]), "r"((a)[2]), "r"((a)[3]), \
          "r"((b)[0]), "r"((b)[1]))

__device__ __forceinline__ uint32_t packbf(__nv_bfloat16 x, __nv_bfloat16 y) {
    uint32_t o;
    asm("mov.b32 %0, {%1, %2};" : "=r"(o)
        : "h"(*(unsigned short*)&x), "h"(*(unsigned short*)&y));
    return o;
}
// split two floats into packed bf16 hi pair + lo (residual) pair
__device__ __forceinline__ void split2(float x, float y, uint32_t& hp, uint32_t& lp) {
    __nv_bfloat16 hx = __float2bfloat16(x), hy = __float2bfloat16(y);
    __nv_bfloat16 lx = __float2bfloat16(x - __bfloat162float(hx));
    __nv_bfloat16 ly = __float2bfloat16(y - __bfloat162float(hy));
    hp = packbf(hx, hy);
    lp = packbf(lx, ly);
}

// ---------------------------------------------------------------------------
// Conversion: fp32 [rows x 1024] -> bf16x3 [rows x 3072].
// patB=0 (A-pattern): segs hi,hi,lo.  patB=1 (B-pattern): segs hi,lo,hi.
// ---------------------------------------------------------------------------
__global__ __launch_bounds__(256) void cvt_kernel(const float* __restrict__ src,
                                                  __nv_bfloat16* __restrict__ dst,
                                                  int patB) {
    const int row = blockIdx.x;
    const int kc = threadIdx.x * 4;
    float4 v = *(const float4*)(src + row * EMB + kc);
    uint32_t h0, l0, h1, l1;
    split2(v.x, v.y, h0, l0);
    split2(v.z, v.w, h1, l1);
    uint2 hv = make_uint2(h0, h1);
    uint2 lv = make_uint2(l0, l1);
    __nv_bfloat16* base = dst + (size_t)row * KEFF + kc;
    *(uint2*)(base)            = hv;
    *(uint2*)(base + EMB)      = patB ? lv : hv;
    *(uint2*)(base + 2 * EMB)  = patB ? hv : lv;
}

// ---------------------------------------------------------------------------
// mma.sync bf16 GEMM: C[m][n] = sum_k A[m][k]*B[n][k], K=3072.
// Block tile 128x128, 8 warps (2x4), warp 64x32, K-chunk 64, 2-stage dyn smem.
// MODE 0: qkv epilogue -> bf16 hi/lo q/k/v buffers. MODE 1: fp32 out + bias.
// ---------------------------------------------------------------------------
#define TILE_M 128
#define TILE_N 128
#define KCH 64
#define NCHUNK (KEFF / KCH)   // 48
#define G_STRIDE 72
#define G_SB (G_STRIDE*2)     // 144 B row stride
#define G_MATB (128*G_SB)     // 18432 B per matrix per stage
#define G_SMEM (4*G_MATB)     // 73728

template <int MODE>
__global__ __launch_bounds__(256, 1) void gemm_kernel(const __nv_bfloat16* __restrict__ A,
                                                      const __nv_bfloat16* __restrict__ B,
                                                      const float* __restrict__ bias,
                                                      float* __restrict__ out) {
    extern __shared__ char gsm[];
    const uint32_t sbase = smem_u32(gsm);

    const int tid = threadIdx.x;
    const int wid = tid >> 5, lane = tid & 31;
    const int m0 = blockIdx.y * TILE_M;
    const int n0 = blockIdx.x * TILE_N;
    const int warp_m = (wid >> 2) * 64;
    const int warp_n = (wid & 3) * 32;

    const char* Ab = (const char*)A + (size_t)m0 * KROWB;
    const char* Bb = (const char*)B + (size_t)n0 * KROWB;

    const int a_row = lane & 15;
    const int a_kof = (lane >> 4) << 3;
    const int b_row = (lane & 7) + ((lane & 16) >> 1);
    const int b_kof = ((lane >> 3) & 1) << 3;

    float acc[4][4][4];
    #pragma unroll
    for (int i = 0; i < 4; i++)
        #pragma unroll
        for (int j = 0; j < 4; j++)
            #pragma unroll
            for (int r = 0; r < 4; r++) acc[i][j][r] = 0.0f;

    auto load_chunk = [&](int c, int s) {
        const uint32_t da = sbase + s * G_MATB;
        const uint32_t db = sbase + 2 * G_MATB + s * G_MATB;
        const size_t ko = (size_t)c * (KCH * 2);
        #pragma unroll
        for (int i = 0; i < 4; i++) {
            int u = tid + i * 256;
            int r = u >> 3, seg = (u & 7) * 16;
            CP_ASYNC16(da + r * G_SB + seg, Ab + (size_t)r * KROWB + ko + seg);
        }
        #pragma unroll
        for (int i = 0; i < 4; i++) {
            int u = tid + i * 256;
            int r = u >> 3, seg = (u & 7) * 16;
            CP_ASYNC16(db + r * G_SB + seg, Bb + (size_t)r * KROWB + ko + seg);
        }
        CP_COMMIT();
    };

    load_chunk(0, 0);
    int s = 0;
    for (int c = 0; c < NCHUNK; c++) {
        if (c + 1 < NCHUNK) { load_chunk(c + 1, s ^ 1); CP_WAIT1(); }
        else CP_WAIT0();
        __syncthreads();

        const uint32_t da = sbase + s * G_MATB;
        const uint32_t db = sbase + 2 * G_MATB + s * G_MATB;
        #pragma unroll
        for (int k0 = 0; k0 < KCH; k0 += 16) {
            uint32_t af[4][4], bf[4][2];
            #pragma unroll
            for (int i = 0; i < 4; i++) {
                uint32_t addr = da + (warp_m + i * 16 + a_row) * G_SB + (k0 + a_kof) * 2;
                LDSM_X4(af[i][0], af[i][1], af[i][2], af[i][3], addr);
            }
            #pragma unroll
            for (int j2 = 0; j2 < 2; j2++) {
                uint32_t addr = db + (warp_n + j2 * 16 + b_row) * G_SB + (k0 + b_kof) * 2;
                LDSM_X4(bf[j2*2][0], bf[j2*2][1], bf[j2*2+1][0], bf[j2*2+1][1], addr);
            }
            #pragma unroll
            for (int i = 0; i < 4; i++)
                #pragma unroll
                for (int j = 0; j < 4; j++)
                    MMA16816(acc[i][j], af[i], bf[j]);
        }
        __syncthreads();
        s ^= 1;
    }

    // Epilogue
    const int sec = n0 >> 10;
    const float sc = (MODE == 0 && sec == 0) ? SCALING : 1.0f;
    __nv_bfloat16* hb = (sec == 0) ? g_qh : (sec == 1) ? g_kh : g_vh;
    __nv_bfloat16* lb = (sec == 0) ? g_ql : (sec == 1) ? g_kl : g_vl;

    #pragma unroll
    for (int i = 0; i < 4; i++) {
        #pragma unroll
        for (int j = 0; j < 4; j++) {
            const int f = n0 + warp_n + j * 8 + (lane & 3) * 2;
            const float b0 = bias[f], b1 = bias[f + 1];
            #pragma unroll
            for (int half = 0; half < 2; half++) {
                const int m = m0 + warp_m + i * 16 + (lane >> 2) + half * 8;
                float ox = (acc[i][j][half * 2 + 0] + b0) * sc;
                float oy = (acc[i][j][half * 2 + 1] + b1) * sc;
                if (MODE == 0) {
                    const int t = m >> 1, bq = m & 1;
                    const int rel = f & 1023, h = rel >> 6, d = rel & 63;
                    size_t idx = (((size_t)(bq * 16 + h) * TLEN + t) * HD + d);
                    uint32_t hp, lp;
                    split2(ox, oy, hp, lp);
                    *(uint32_t*)(hb + idx) = hp;
                    *(uint32_t*)(lb + idx) = lp;
                } else {
                    *(float2*)(out + (size_t)m * EMB + f) = make_float2(ox, oy);
                }
            }
        }
    }
}

// ---------------------------------------------------------------------------
// Tensor-core flash attention.
// Block = (head, 128-q-tile). 8 warps x 16 q-rows. KV chunk = 128 keys,
// double-buffered cp.async. 3-term bf16 hi/lo for both QK^T and PV.
// Epilogue writes outproj A-pattern (hi,hi,lo) into g_attna.
// ---------------------------------------------------------------------------
#define AT_STRIDE 72
#define AT_SB (AT_STRIDE*2)      // 144 B
#define AT_MATB (128*AT_SB)      // 18432 B per matrix
#define AT_STAGEB (4*AT_MATB)    // 73728 B (Khi,Klo,Vhi,Vlo)
#define AT_SMEM (2*AT_STAGEB)    // 147456

__global__ __launch_bounds__(256, 1) void attn_tc_kernel() {
    extern __shared__ char asmb[];
    const uint32_t sb = smem_u32(asmb);
    const int tid = threadIdx.x;
    const int wid = tid >> 5, lane = tid & 31;
    const int head = blockIdx.y;
    const int qb = blockIdx.x * 128;
    const int wr0 = wid * 16;
    const int r = lane >> 2, cb = (lane & 3) * 2;

    const int b_row = (lane & 7) + ((lane & 16) >> 1);
    const int b_kof = ((lane >> 3) & 1) << 3;
    const int v_row = lane & 15;
    const int v_cof = (lane >> 4) << 3;

    // Q fragments direct from gmem (rows wr0..wr0+15, d 0..63, hi+lo)
    const __nv_bfloat16* qhp = g_qh + ((size_t)head * TLEN + qb + wr0) * HD;
    const __nv_bfloat16* qlp = g_ql + ((size_t)head * TLEN + qb + wr0) * HD;
    uint32_t qfh[4][4], qfl[4][4];
    #pragma unroll
    for (int ks = 0; ks < 4; ks++) {
        qfh[ks][0] = *(const uint32_t*)(qhp + (size_t)(r    ) * HD + ks * 16 + cb);
        qfh[ks][1] = *(const uint32_t*)(qhp + (size_t)(r + 8) * HD + ks * 16 + cb);
        qfh[ks][2] = *(const uint32_t*)(qhp + (size_t)(r    ) * HD + ks * 16 + 8 + cb);
        qfh[ks][3] = *(const uint32_t*)(qhp + (size_t)(r + 8) * HD + ks * 16 + 8 + cb);
        qfl[ks][0] = *(const uint32_t*)(qlp + (size_t)(r    ) * HD + ks * 16 + cb);
        qfl[ks][1] = *(const uint32_t*)(qlp + (size_t)(r + 8) * HD + ks * 16 + cb);
        qfl[ks][2] = *(const uint32_t*)(qlp + (size_t)(r    ) * HD + ks * 16 + 8 + cb);
        qfl[ks][3] = *(const uint32_t*)(qlp + (size_t)(r + 8) * HD + ks * 16 + 8 + cb);
    }

    const char* Khg = (const char*)(g_kh + (size_t)head * TLEN * HD);
    const char* Klg = (const char*)(g_kl + (size_t)head * TLEN * HD);
    const char* Vhg = (const char*)(g_vh + (size_t)head * TLEN * HD);
    const char* Vlg = (const char*)(g_vl + (size_t)head * TLEN * HD);

    auto load_chunk = [&](int c, int s) {
        const uint32_t st = sb + s * AT_STAGEB;
        const size_t go = (size_t)c * 128 * (HD * 2);   // 128 keys * 128 B
        #pragma unroll
        for (int i = 0; i < 4; i++) {
            int u = tid + i * 256;
            int rr = u >> 3, seg = (u & 7) * 16;
            uint32_t doff = rr * AT_SB + seg;
            size_t soff = go + (size_t)rr * (HD * 2) + seg;
            CP_ASYNC16(st + 0 * AT_MATB + doff, Khg + soff);
            CP_ASYNC16(st + 1 * AT_MATB + doff, Klg + soff);
            CP_ASYNC16(st + 2 * AT_MATB + doff, Vhg + soff);
            CP_ASYNC16(st + 3 * AT_MATB + doff, Vlg + soff);
        }
        CP_COMMIT();
    };

    float m0 = -3.0e38f, m1 = -3.0e38f, l0 = 0.0f, l1 = 0.0f;
    float O[8][4];
    #pragma unroll
    for (int nt = 0; nt < 8; nt++)
        #pragma unroll
        for (int j = 0; j < 4; j++) O[nt][j] = 0.0f;

    load_chunk(0, 0);
    int s = 0;
    for (int c = 0; c < TLEN / 128; c++) {
        if (c + 1 < TLEN / 128) { load_chunk(c + 1, s ^ 1); CP_WAIT1(); }
        else CP_WAIT0();
        __syncthreads();

        const uint32_t st = sb + s * AT_STAGEB;

        // ---- S = Q K^T (3-term), 8 keygroups of 16 keys ----
        float sacc[8][8];
        #pragma unroll
        for (int kg = 0; kg < 8; kg++)
            #pragma unroll
            for (int j = 0; j < 8; j++) sacc[kg][j] = 0.0f;

        #pragma unroll
        for (int kg = 0; kg < 8; kg++) {
            #pragma unroll
            for (int ks = 0; ks < 4; ks++) {
                uint32_t bh[4], bl[4];
                uint32_t ah = st + 0 * AT_MATB + (kg * 16 + b_row) * AT_SB + (ks * 16 + b_kof) * 2;
                uint32_t al = st + 1 * AT_MATB + (kg * 16 + b_row) * AT_SB + (ks * 16 + b_kof) * 2;
                LDSM_X4(bh[0], bh[1], bh[2], bh[3], ah);
                LDSM_X4(bl[0], bl[1], bl[2], bl[3], al);
                MMA16816(&sacc[kg][0], qfh[ks], bh);
                MMA16816(&sacc[kg][4], qfh[ks], bh + 2);
                MMA16816(&sacc[kg][0], qfh[ks], bl);
                MMA16816(&sacc[kg][4], qfh[ks], bl + 2);
                MMA16816(&sacc[kg][0], qfl[ks], bh);
                MMA16816(&sacc[kg][4], qfl[ks], bh + 2);
            }
        }

        // ---- online softmax (rows r and r+8) ----
        float mx0 = -3.0e38f, mx1 = -3.0e38f;
        #pragma unroll
        for (int kg = 0; kg < 8; kg++) {
            mx0 = fmaxf(mx0, fmaxf(fmaxf(sacc[kg][0], sacc[kg][1]),
                                   fmaxf(sacc[kg][4], sacc[kg][5])));
            mx1 = fmaxf(mx1, fmaxf(fmaxf(sacc[kg][2], sacc[kg][3]),
                                   fmaxf(sacc[kg][6], sacc[kg][7])));
        }
        mx0 = fmaxf(mx0, __shfl_xor_sync(0xffffffff, mx0, 1));
        mx0 = fmaxf(mx0, __shfl_xor_sync(0xffffffff, mx0, 2));
        mx1 = fmaxf(mx1, __shfl_xor_sync(0xffffffff, mx1, 1));
        mx1 = fmaxf(mx1, __shfl_xor_sync(0xffffffff, mx1, 2));

        float mn0 = fmaxf(m0, mx0), mn1 = fmaxf(m1, mx1);
        float al0 = __expf(m0 - mn0), al1 = __expf(m1 - mn1);
        m0 = mn0; m1 = mn1;

        float rs0 = 0.0f, rs1 = 0.0f;
        uint32_t pfh[8][4], pfl[8][4];
        #pragma unroll
        for (int kg = 0; kg < 8; kg++) {
            float p0 = __expf(sacc[kg][0] - mn0), p1 = __expf(sacc[kg][1] - mn0);
            float p2 = __expf(sacc[kg][2] - mn1), p3 = __expf(sacc[kg][3] - mn1);
            float p4 = __expf(sacc[kg][4] - mn0), p5 = __expf(sacc[kg][5] - mn0);
            float p6 = __expf(sacc[kg][6] - mn1), p7 = __expf(sacc[kg][7] - mn1);
            rs0 += p0 + p1 + p4 + p5;
            rs1 += p2 + p3 + p6 + p7;
            split2(p0, p1, pfh[kg][0], pfl[kg][0]);
            split2(p2, p3, pfh[kg][1], pfl[kg][1]);
            split2(p4, p5, pfh[kg][2], pfl[kg][2]);
            split2(p6, p7, pfh[kg][3], pfl[kg][3]);
        }
        rs0 += __shfl_xor_sync(0xffffffff, rs0, 1);
        rs0 += __shfl_xor_sync(0xffffffff, rs0, 2);
        rs1 += __shfl_xor_sync(0xffffffff, rs1, 1);
        rs1 += __shfl_xor_sync(0xffffffff, rs1, 2);
        l0 = l0 * al0 + rs0;
        l1 = l1 * al1 + rs1;

        #pragma unroll
        for (int nt = 0; nt < 8; nt++) {
            O[nt][0] *= al0; O[nt][1] *= al0;
            O[nt][2] *= al1; O[nt][3] *= al1;
        }

        // ---- O += P V (3-term), key k-steps = 8 groups of 16 ----
        #pragma unroll
        for (int kg = 0; kg < 8; kg++) {
            #pragma unroll
            for (int dt = 0; dt < 4; dt++) {
                uint32_t vh[4], vl[4];
                uint32_t ahh = st + 2 * AT_MATB + (kg * 16 + v_row) * AT_SB + (dt * 16 + v_cof) * 2;
                uint32_t all = st + 3 * AT_MATB + (kg * 16 + v_row) * AT_SB + (dt * 16 + v_cof) * 2;
                LDSM_X4_T(vh[0], vh[1], vh[2], vh[3], ahh);
                LDSM_X4_T(vl[0], vl[1], vl[2], vl[3], all);
                MMA16816(O[2*dt],     pfh[kg], vh);
                MMA16816(O[2*dt + 1], pfh[kg], vh + 2);
                MMA16816(O[2*dt],     pfh[kg], vl);
                MMA16816(O[2*dt + 1], pfh[kg], vl + 2);
                MMA16816(O[2*dt],     pfl[kg], vh);
                MMA16816(O[2*dt + 1], pfl[kg], vh + 2);
            }
        }
        __syncthreads();
        s ^= 1;
    }

    // ---- epilogue: normalize, write outproj A-pattern (hi,hi,lo) ----
    const float inv0 = 1.0f / l0, inv1 = 1.0f / l1;
    const int bb = head >> 4, hh = head & 15;
    const int mr0 = (qb + wr0 + r) * 2 + bb;
    const int mr8 = (qb + wr0 + r + 8) * 2 + bb;
    #pragma unroll
    for (int nt = 0; nt < 8; nt++) {
        const int e = hh * 64 + nt * 8 + cb;
        uint32_t hp, lp;
        split2(O[nt][0] * inv0, O[nt][1] * inv0, hp, lp);
        __nv_bfloat16* base = g_attna + (size_t)mr0 * KEFF + e;
        *(uint32_t*)(base)           = hp;
        *(uint32_t*)(base + EMB)     = hp;
        *(uint32_t*)(base + 2*EMB)   = lp;
        split2(O[nt][2] * inv1, O[nt][3] * inv1, hp, lp);
        base = g_attna + (size_t)mr8 * KEFF + e;
        *(uint32_t*)(base)           = hp;
        *(uint32_t*)(base + EMB)     = hp;
        *(uint32_t*)(base + 2*EMB)   = lp;
    }
}

// ---------------------------------------------------------------------------
extern "C" void kernel_launch(void* const* d_in, const int* in_sizes, int n_in,
                              void* d_out, int out_size) {
    (void)in_sizes; (void)n_in; (void)out_size;
    const float* x     = (const float*)d_in[0];
    const float* w_in  = (const float*)d_in[1];
    const float* b_in  = (const float*)d_in[2];
    const float* w_out = (const float*)d_in[3];
    const float* b_out = (const float*)d_in[4];
    float* out = (float*)d_out;

    cudaFuncSetAttribute(gemm_kernel<0>, cudaFuncAttributeMaxDynamicSharedMemorySize, G_SMEM);
    cudaFuncSetAttribute(gemm_kernel<1>, cudaFuncAttributeMaxDynamicSharedMemorySize, G_SMEM);
    cudaFuncSetAttribute(attn_tc_kernel, cudaFuncAttributeMaxDynamicSharedMemorySize, AT_SMEM);

    __nv_bfloat16 *gxa, *gwin, *gwout, *gattna;
    cudaGetSymbolAddress((void**)&gxa, g_xa);
    cudaGetSymbolAddress((void**)&gwin, g_win);
    cudaGetSymbolAddress((void**)&gwout, g_wout);
    cudaGetSymbolAddress((void**)&gattna, g_attna);

    // 1) convert operands to bf16x3
    cvt_kernel<<<MROWS, 256>>>(x, gxa, 0);
    cvt_kernel<<<THREE_E, 256>>>(w_in, gwin, 1);
    cvt_kernel<<<EMB, 256>>>(w_out, gwout, 1);
    // 2) QKV projection -> bf16 hi/lo q/k/v
    gemm_kernel<0><<<dim3(THREE_E / TILE_N, MROWS / TILE_M), 256, G_SMEM>>>(gxa, gwin, b_in, nullptr);
    // 3) tensor-core flash attention -> g_attna (A-pattern)
    attn_tc_kernel<<<dim3(TLEN / 128, BH), 256, AT_SMEM>>>();
    // 4) output projection
    gemm_kernel<1><<<dim3(EMB / TILE_N, MROWS / TILE_M), 256, G_SMEM>>>(gattna, gwout, b_out, out);
}